// round 3
// baseline (speedup 1.0000x reference)
#include <cuda_runtime.h>
#include <cstdint>
#include <cstddef>

static constexpr int MDIM = 8192;   // 4*2048 tokens
static constexpr int KDIM = 4096;
static constexpr int NDIM = 4096;

// ---------------- scratch (alloc-free: __device__ globals) ----------------
__device__ __align__(1024) int8_t g_Aq[(size_t)MDIM * KDIM]; // Xq - 128 (s8)
__device__ __align__(1024) int8_t g_Wq[(size_t)NDIM * KDIM]; // Wq (s8)
__device__ float g_sa[MDIM];   // activation scale per token
__device__ float g_czp[MDIM];  // 128 - zp  per token
__device__ float g_sw[NDIM];   // weight scale per row
__device__ float g_rs[NDIM];   // rowsum of Wq per row (exact int in f32)

// ---------------- PTX helpers ----------------
__device__ __forceinline__ uint32_t smem_u32(const void* p) {
    uint32_t a;
    asm("{ .reg .u64 t; cvta.to.shared.u64 t, %1; cvt.u32.u64 %0, t; }" : "=r"(a) : "l"(p));
    return a;
}
#define CPA16(s, g) asm volatile("cp.async.cg.shared.global [%0], [%1], 16;" :: "r"(s), "l"(g))
#define CP_COMMIT()  asm volatile("cp.async.commit_group;" ::: "memory")
#define CP_WAIT(n)   asm volatile("cp.async.wait_group %0;" :: "n"(n) : "memory")
#define LDSM4(r0, r1, r2, r3, addr) \
    asm volatile("ldmatrix.sync.aligned.m8n8.x4.shared.b16 {%0,%1,%2,%3}, [%4];" \
                 : "=r"(r0), "=r"(r1), "=r"(r2), "=r"(r3) : "r"(addr))
#define IMMA(c, a, b) \
    asm volatile("mma.sync.aligned.m16n8k32.row.col.s32.s8.s8.s32 " \
                 "{%0,%1,%2,%3}, {%4,%5,%6,%7}, {%8,%9}, {%0,%1,%2,%3};" \
                 : "+r"((c)[0]), "+r"((c)[1]), "+r"((c)[2]), "+r"((c)[3]) \
                 : "r"((a)[0]), "r"((a)[1]), "r"((a)[2]), "r"((a)[3]), \
                   "r"((b)[0]), "r"((b)[1]))

// ---------------- quantization kernels (unchanged; proven correct) ----------------
__global__ void __launch_bounds__(256) quant_x_kernel(const float* __restrict__ x) {
    const int m = blockIdx.x;
    const int t = threadIdx.x;
    const float4* row = reinterpret_cast<const float4*>(x + (size_t)m * KDIM);
    float4 v[4];
    float mn = 3.4e38f, mx = -3.4e38f;
#pragma unroll
    for (int i = 0; i < 4; i++) {
        v[i] = row[t * 4 + i];
        mn = fminf(mn, fminf(fminf(v[i].x, v[i].y), fminf(v[i].z, v[i].w)));
        mx = fmaxf(mx, fmaxf(fmaxf(v[i].x, v[i].y), fmaxf(v[i].z, v[i].w)));
    }
#pragma unroll
    for (int o = 16; o > 0; o >>= 1) {
        mn = fminf(mn, __shfl_xor_sync(0xffffffffu, mn, o));
        mx = fmaxf(mx, __shfl_xor_sync(0xffffffffu, mx, o));
    }
    __shared__ float smn[8], smx[8];
    if ((t & 31) == 0) { smn[t >> 5] = mn; smx[t >> 5] = mx; }
    __syncthreads();
    mn = smn[0]; mx = smx[0];
#pragma unroll
    for (int i = 1; i < 8; i++) { mn = fminf(mn, smn[i]); mx = fmaxf(mx, smx[i]); }

    const float rng = mx - mn;
    const float s = (rng > 0.0f) ? __fdiv_rn(rng, 255.0f) : 1.0f;
    const float zp = rintf(__fdiv_rn(-mn, s));

    uint32_t pk[4];
#pragma unroll
    for (int i = 0; i < 4; i++) {
        int q0 = (int)(fminf(fmaxf(rintf(__fdiv_rn(v[i].x, s)) + zp, 0.0f), 255.0f)) - 128;
        int q1 = (int)(fminf(fmaxf(rintf(__fdiv_rn(v[i].y, s)) + zp, 0.0f), 255.0f)) - 128;
        int q2 = (int)(fminf(fmaxf(rintf(__fdiv_rn(v[i].z, s)) + zp, 0.0f), 255.0f)) - 128;
        int q3 = (int)(fminf(fmaxf(rintf(__fdiv_rn(v[i].w, s)) + zp, 0.0f), 255.0f)) - 128;
        pk[i] = (uint32_t)(q0 & 255) | ((uint32_t)(q1 & 255) << 8) |
                ((uint32_t)(q2 & 255) << 16) | ((uint32_t)(q3 & 255) << 24);
    }
    *reinterpret_cast<uint4*>(g_Aq + (size_t)m * KDIM + t * 16) =
        make_uint4(pk[0], pk[1], pk[2], pk[3]);
    if (t == 0) { g_sa[m] = s; g_czp[m] = 128.0f - zp; }
}

__global__ void __launch_bounds__(256) quant_w_kernel(const float* __restrict__ w) {
    const int n = blockIdx.x;
    const int t = threadIdx.x;
    const float4* row = reinterpret_cast<const float4*>(w + (size_t)n * KDIM);
    float4 v[4];
    float amax = 0.0f;
#pragma unroll
    for (int i = 0; i < 4; i++) {
        v[i] = row[t * 4 + i];
        amax = fmaxf(amax, fmaxf(fmaxf(fabsf(v[i].x), fabsf(v[i].y)),
                                 fmaxf(fabsf(v[i].z), fabsf(v[i].w))));
    }
#pragma unroll
    for (int o = 16; o > 0; o >>= 1)
        amax = fmaxf(amax, __shfl_xor_sync(0xffffffffu, amax, o));
    __shared__ float sm[8];
    __shared__ int ssum[8];
    if ((t & 31) == 0) sm[t >> 5] = amax;
    __syncthreads();
    amax = sm[0];
#pragma unroll
    for (int i = 1; i < 8; i++) amax = fmaxf(amax, sm[i]);

    const float s = (amax > 0.0f) ? __fdiv_rn(amax, 127.0f) : 1.0f;

    uint32_t pk[4];
    int rsum = 0;
#pragma unroll
    for (int i = 0; i < 4; i++) {
        int q0 = (int)fminf(fmaxf(rintf(__fdiv_rn(v[i].x, s)), -127.0f), 127.0f);
        int q1 = (int)fminf(fmaxf(rintf(__fdiv_rn(v[i].y, s)), -127.0f), 127.0f);
        int q2 = (int)fminf(fmaxf(rintf(__fdiv_rn(v[i].z, s)), -127.0f), 127.0f);
        int q3 = (int)fminf(fmaxf(rintf(__fdiv_rn(v[i].w, s)), -127.0f), 127.0f);
        rsum += q0 + q1 + q2 + q3;
        pk[i] = (uint32_t)(q0 & 255) | ((uint32_t)(q1 & 255) << 8) |
                ((uint32_t)(q2 & 255) << 16) | ((uint32_t)(q3 & 255) << 24);
    }
    *reinterpret_cast<uint4*>(g_Wq + (size_t)n * KDIM + t * 16) =
        make_uint4(pk[0], pk[1], pk[2], pk[3]);

#pragma unroll
    for (int o = 16; o > 0; o >>= 1)
        rsum += __shfl_xor_sync(0xffffffffu, rsum, o);
    if ((t & 31) == 0) ssum[t >> 5] = rsum;
    __syncthreads();
    if (t == 0) {
        int tot = 0;
#pragma unroll
        for (int i = 0; i < 8; i++) tot += ssum[i];
        g_sw[n] = s;
        g_rs[n] = (float)tot;
    }
}

// ---------------- GEMM: s8 IMMA, 128x128x128, 4-stage cp.async, 1 CTA/SM ----------------
static constexpr int BM = 128, BN = 128, BK = 128;
static constexpr int STAGES = 4;
static constexpr int NCHUNK = KDIM / BK;                   // 32
static constexpr int A_BYTES = BM * BK;                    // 16384
static constexpr int STAGE_BYTES = BM * BK + BN * BK;      // 32768
static constexpr uint32_t GEMM_SMEM = STAGES * STAGE_BYTES;  // 131072

__global__ void __launch_bounds__(256)
gemm_kernel(const float* __restrict__ bias, float* __restrict__ out) {
    extern __shared__ int8_t smem[];
    const uint32_t sbase = smem_u32(smem);
    const int tid = threadIdx.x;
    const int wid = tid >> 5;
    const int lane = tid & 31;
    const int bm = blockIdx.y * BM;
    const int bn = blockIdx.x * BN;

    // ---- cp.async setup: rows of 128B = 8 x 16B units, phys_unit = u ^ (row&7) ----
    const int r  = tid >> 1;            // 0..127 (row within tile)
    const int u0 = (tid & 1) * 4;       // first of 4 units handled by this thread
    const int8_t* gA = g_Aq + (size_t)(bm + r) * KDIM + u0 * 16;
    const int8_t* gB = g_Wq + (size_t)(bn + r) * KDIM + u0 * 16;
    uint32_t sAaddr[4], sBaddr[4];
#pragma unroll
    for (int j = 0; j < 4; j++) {
        const uint32_t p = (uint32_t)((u0 + j) ^ (r & 7)) * 16;
        sAaddr[j] = sbase + (uint32_t)r * 128 + p;
        sBaddr[j] = sAaddr[j] + A_BYTES;
    }

    // ---- warp tiling: 2 (M) x 4 (N); warp tile 64x32 ----
    const int warp_m = (wid & 1) << 6;    // 0 / 64
    const int warp_n = (wid >> 1) << 5;   // 0/32/64/96
    const int lr = lane & 7;
    // A ldmatrix lane constants: matrix i = lane>>3: (i&1)->+8 rows, (i>>1)->k-16B-half
    const int aRow = warp_m + ((lane >> 3) & 1) * 8 + lr;
    const int aHi  = lane >> 4;           // unit lsb within k-step
    const int aX   = aRow & 7;
    const uint32_t aBase = (uint32_t)aRow * 128;
    // B ldmatrix lane constants: matrix i: (i&1)->k-half, (i>>1)->+8 n-rows
    const int bRow = warp_n + (lane >> 4) * 8 + lr;
    const int bHi  = (lane >> 3) & 1;
    const int bX   = bRow & 7;
    const uint32_t bBase = (uint32_t)A_BYTES + (uint32_t)bRow * 128;

    int acc[4][4][4];
#pragma unroll
    for (int i = 0; i < 4; i++)
#pragma unroll
        for (int j = 0; j < 4; j++)
#pragma unroll
            for (int q = 0; q < 4; q++) acc[i][j][q] = 0;

    auto issue_load = [&](int c, uint32_t so) {
        const size_t go = (size_t)c * BK;
#pragma unroll
        for (int j = 0; j < 4; j++) CPA16(sAaddr[j] + so, gA + go + j * 16);
#pragma unroll
        for (int j = 0; j < 4; j++) CPA16(sBaddr[j] + so, gB + go + j * 16);
    };

    issue_load(0, 0 * STAGE_BYTES); CP_COMMIT();
    issue_load(1, 1 * STAGE_BYTES); CP_COMMIT();
    issue_load(2, 2 * STAGE_BYTES); CP_COMMIT();

    uint32_t a[2][4][4], b[2][4][2];

    auto load_frags = [&](int s, uint32_t st, int buf) {
        const uint32_t ua = (uint32_t)(((s << 1) + aHi) ^ aX) * 16;
#pragma unroll
        for (int mt = 0; mt < 4; mt++) {
            const uint32_t ad = st + aBase + (uint32_t)mt * 2048 + ua;
            LDSM4(a[buf][mt][0], a[buf][mt][1], a[buf][mt][2], a[buf][mt][3], ad);
        }
        const uint32_t ub = (uint32_t)(((s << 1) + bHi) ^ bX) * 16;
#pragma unroll
        for (int ng = 0; ng < 2; ng++) {
            const uint32_t bd = st + bBase + (uint32_t)ng * 2048 + ub;
            LDSM4(b[buf][2 * ng][0], b[buf][2 * ng][1],
                  b[buf][2 * ng + 1][0], b[buf][2 * ng + 1][1], bd);
        }
    };

    int stage = 0;       // stage index of chunk c
    int nstage = 3;      // stage index for chunk c+3
    for (int c = 0; c < NCHUNK; c++) {
        CP_WAIT(2);
        __syncthreads();
        const uint32_t st = sbase + (uint32_t)stage * STAGE_BYTES;

        load_frags(0, st, 0);

        if (c + 3 < NCHUNK) issue_load(c + 3, (uint32_t)nstage * STAGE_BYTES);
        CP_COMMIT();

#pragma unroll
        for (int s = 0; s < 4; s++) {
            if (s < 3) load_frags(s + 1, st, (s + 1) & 1);
            const int cur = s & 1;
#pragma unroll
            for (int mt = 0; mt < 4; mt++)
#pragma unroll
                for (int nt = 0; nt < 4; nt++)
                    IMMA(acc[mt][nt], a[cur][mt], b[cur][nt]);
        }

        if (++stage == STAGES) stage = 0;
        if (++nstage == STAGES) nstage = 0;
    }

    // ---- epilogue: acc + czp[m]*rs[n], scale, bias ----
#pragma unroll
    for (int mt = 0; mt < 4; mt++) {
        const int r0 = bm + warp_m + mt * 16 + (lane >> 2);
        const float sa0 = g_sa[r0], cz0 = g_czp[r0];
        const float sa1 = g_sa[r0 + 8], cz1 = g_czp[r0 + 8];
        float* o0 = out + (size_t)r0 * NDIM + bn;
        float* o1 = o0 + (size_t)8 * NDIM;
#pragma unroll
        for (int nt = 0; nt < 4; nt++) {
            const int ncol = warp_n + nt * 8 + ((lane & 3) << 1);
            const int n = bn + ncol;
            const float sw0 = g_sw[n], sw1 = g_sw[n + 1];
            const float rs0 = g_rs[n], rs1 = g_rs[n + 1];
            const float b0 = __ldg(bias + n), b1 = __ldg(bias + n + 1);
            const int* cc = acc[mt][nt];
            float2 y0, y1;
            y0.x = ((float)cc[0] + cz0 * rs0) * (sa0 * sw0) + b0;
            y0.y = ((float)cc[1] + cz0 * rs1) * (sa0 * sw1) + b1;
            y1.x = ((float)cc[2] + cz1 * rs0) * (sa1 * sw0) + b0;
            y1.y = ((float)cc[3] + cz1 * rs1) * (sa1 * sw1) + b1;
            *reinterpret_cast<float2*>(o0 + ncol) = y0;
            *reinterpret_cast<float2*>(o1 + ncol) = y1;
        }
    }
}

// ---------------- host launch ----------------
extern "C" void kernel_launch(void* const* d_in, const int* in_sizes, int n_in,
                              void* d_out, int out_size) {
    (void)in_sizes; (void)n_in; (void)out_size;
    const float* x    = (const float*)d_in[0];
    const float* w    = (const float*)d_in[1];
    const float* bias = (const float*)d_in[2];
    float* out = (float*)d_out;

    quant_x_kernel<<<MDIM, 256>>>(x);
    quant_w_kernel<<<NDIM, 256>>>(w);

    static int smem_set = 0;
    if (!smem_set) {
        cudaFuncSetAttribute(gemm_kernel, cudaFuncAttributeMaxDynamicSharedMemorySize,
                             GEMM_SMEM);
        smem_set = 1;
    }
    gemm_kernel<<<dim3(NDIM / BN, MDIM / BM), 256, GEMM_SMEM>>>(bias, out);
}

// round 4
// speedup vs baseline: 1.7844x; 1.7844x over previous
#include <cuda_runtime.h>
#include <cuda_bf16.h>
#include <cstdint>
#include <cstddef>

static constexpr int MDIM = 8192;   // 4*2048 tokens
static constexpr int KDIM = 4096;
static constexpr int NDIM = 4096;

// ---------------- scratch (alloc-free: __device__ globals) ----------------
__device__ __align__(1024) __nv_bfloat16 g_Aq[(size_t)MDIM * KDIM]; // Xq - zp (exact ints)
__device__ __align__(1024) __nv_bfloat16 g_Wq[(size_t)NDIM * KDIM]; // Wq (exact ints)
__device__ float g_sa[MDIM];   // activation scale per token
__device__ float g_sw[NDIM];   // weight scale per row

// ---------------- PTX helpers ----------------
__device__ __forceinline__ uint32_t smem_u32(const void* p) {
    uint32_t a;
    asm("{ .reg .u64 t; cvta.to.shared.u64 t, %1; cvt.u32.u64 %0, t; }" : "=r"(a) : "l"(p));
    return a;
}
#define CPA16(s, g) asm volatile("cp.async.cg.shared.global [%0], [%1], 16;" :: "r"(s), "l"(g))
#define CP_COMMIT()  asm volatile("cp.async.commit_group;" ::: "memory")
#define CP_WAIT(n)   asm volatile("cp.async.wait_group %0;" :: "n"(n) : "memory")
#define LDSM4(r0, r1, r2, r3, addr) \
    asm volatile("ldmatrix.sync.aligned.m8n8.x4.shared.b16 {%0,%1,%2,%3}, [%4];" \
                 : "=r"(r0), "=r"(r1), "=r"(r2), "=r"(r3) : "r"(addr))
#define HMMA(c, a, b) \
    asm volatile("mma.sync.aligned.m16n8k16.row.col.f32.bf16.bf16.f32 " \
                 "{%0,%1,%2,%3}, {%4,%5,%6,%7}, {%8,%9}, {%0,%1,%2,%3};" \
                 : "+f"((c)[0]), "+f"((c)[1]), "+f"((c)[2]), "+f"((c)[3]) \
                 : "r"((a)[0]), "r"((a)[1]), "r"((a)[2]), "r"((a)[3]), \
                   "r"((b)[0]), "r"((b)[1]))

// ---------------- quantization kernels ----------------
// Per-token asymmetric uint8; store (Xq - zp) as exact bf16 ints.
__global__ void __launch_bounds__(256) quant_x_kernel(const float* __restrict__ x) {
    const int m = blockIdx.x;
    const int t = threadIdx.x;
    const float4* row = reinterpret_cast<const float4*>(x + (size_t)m * KDIM);
    float4 v[4];
    float mn = 3.4e38f, mx = -3.4e38f;
#pragma unroll
    for (int i = 0; i < 4; i++) {
        v[i] = row[t * 4 + i];
        mn = fminf(mn, fminf(fminf(v[i].x, v[i].y), fminf(v[i].z, v[i].w)));
        mx = fmaxf(mx, fmaxf(fmaxf(v[i].x, v[i].y), fmaxf(v[i].z, v[i].w)));
    }
#pragma unroll
    for (int o = 16; o > 0; o >>= 1) {
        mn = fminf(mn, __shfl_xor_sync(0xffffffffu, mn, o));
        mx = fmaxf(mx, __shfl_xor_sync(0xffffffffu, mx, o));
    }
    __shared__ float smn[8], smx[8];
    if ((t & 31) == 0) { smn[t >> 5] = mn; smx[t >> 5] = mx; }
    __syncthreads();
    mn = smn[0]; mx = smx[0];
#pragma unroll
    for (int i = 1; i < 8; i++) { mn = fminf(mn, smn[i]); mx = fmaxf(mx, smx[i]); }

    const float rng = mx - mn;
    const float s = (rng > 0.0f) ? __fdiv_rn(rng, 255.0f) : 1.0f;
    const float zp = rintf(__fdiv_rn(-mn, s));

    __nv_bfloat16* o = g_Aq + (size_t)m * KDIM + t * 16;
#pragma unroll
    for (int i = 0; i < 4; i++) {
        float q0 = fminf(fmaxf(rintf(__fdiv_rn(v[i].x, s)) + zp, 0.0f), 255.0f) - zp;
        float q1 = fminf(fmaxf(rintf(__fdiv_rn(v[i].y, s)) + zp, 0.0f), 255.0f) - zp;
        float q2 = fminf(fmaxf(rintf(__fdiv_rn(v[i].z, s)) + zp, 0.0f), 255.0f) - zp;
        float q3 = fminf(fmaxf(rintf(__fdiv_rn(v[i].w, s)) + zp, 0.0f), 255.0f) - zp;
        __nv_bfloat162 p0 = __halves2bfloat162(__float2bfloat16_rn(q0), __float2bfloat16_rn(q1));
        __nv_bfloat162 p1 = __halves2bfloat162(__float2bfloat16_rn(q2), __float2bfloat16_rn(q3));
        *reinterpret_cast<__nv_bfloat162*>(o + i * 4)     = p0;
        *reinterpret_cast<__nv_bfloat162*>(o + i * 4 + 2) = p1;
    }
    if (t == 0) g_sa[m] = s;
}

// Per-row symmetric int8 weights; store Wq as exact bf16 ints.
__global__ void __launch_bounds__(256) quant_w_kernel(const float* __restrict__ w) {
    const int n = blockIdx.x;
    const int t = threadIdx.x;
    const float4* row = reinterpret_cast<const float4*>(w + (size_t)n * KDIM);
    float4 v[4];
    float amax = 0.0f;
#pragma unroll
    for (int i = 0; i < 4; i++) {
        v[i] = row[t * 4 + i];
        amax = fmaxf(amax, fmaxf(fmaxf(fabsf(v[i].x), fabsf(v[i].y)),
                                 fmaxf(fabsf(v[i].z), fabsf(v[i].w))));
    }
#pragma unroll
    for (int o = 16; o > 0; o >>= 1)
        amax = fmaxf(amax, __shfl_xor_sync(0xffffffffu, amax, o));
    __shared__ float sm[8];
    if ((t & 31) == 0) sm[t >> 5] = amax;
    __syncthreads();
    amax = sm[0];
#pragma unroll
    for (int i = 1; i < 8; i++) amax = fmaxf(amax, sm[i]);

    const float s = (amax > 0.0f) ? __fdiv_rn(amax, 127.0f) : 1.0f;

    __nv_bfloat16* o = g_Wq + (size_t)n * KDIM + t * 16;
#pragma unroll
    for (int i = 0; i < 4; i++) {
        float q0 = fminf(fmaxf(rintf(__fdiv_rn(v[i].x, s)), -127.0f), 127.0f);
        float q1 = fminf(fmaxf(rintf(__fdiv_rn(v[i].y, s)), -127.0f), 127.0f);
        float q2 = fminf(fmaxf(rintf(__fdiv_rn(v[i].z, s)), -127.0f), 127.0f);
        float q3 = fminf(fmaxf(rintf(__fdiv_rn(v[i].w, s)), -127.0f), 127.0f);
        __nv_bfloat162 p0 = __halves2bfloat162(__float2bfloat16_rn(q0), __float2bfloat16_rn(q1));
        __nv_bfloat162 p1 = __halves2bfloat162(__float2bfloat16_rn(q2), __float2bfloat16_rn(q3));
        *reinterpret_cast<__nv_bfloat162*>(o + i * 4)     = p0;
        *reinterpret_cast<__nv_bfloat162*>(o + i * 4 + 2) = p1;
    }
    if (t == 0) g_sw[n] = s;
}

// ---------------- GEMM: bf16 HMMA, 128x128x64(elts), 4-stage cp.async ----------------
static constexpr int BM = 128, BN = 128;
static constexpr int BKB = 128;                            // K bytes per chunk (64 bf16)
static constexpr int STAGES = 4;
static constexpr int NCHUNK = (KDIM * 2) / BKB;            // 64
static constexpr int A_BYTES = BM * BKB;                   // 16384
static constexpr int STAGE_BYTES = (BM + BN) * BKB;        // 32768
static constexpr uint32_t GEMM_SMEM = STAGES * STAGE_BYTES;  // 131072
static constexpr size_t ROWB = (size_t)KDIM * 2;           // bytes per logical row

__global__ void __launch_bounds__(256)
gemm_kernel(const float* __restrict__ bias, float* __restrict__ out) {
    extern __shared__ int8_t smem[];
    const uint32_t sbase = smem_u32(smem);
    const int tid = threadIdx.x;
    const int wid = tid >> 5;
    const int lane = tid & 31;
    const int bm = blockIdx.y * BM;
    const int bn = blockIdx.x * BN;

    // ---- cp.async: rows of 128B = 8 x 16B units, phys_unit = u ^ (row&7) ----
    const int r  = tid >> 1;            // 0..127
    const int u0 = (tid & 1) * 4;       // first of 4 units
    const char* gA = (const char*)g_Aq + (size_t)(bm + r) * ROWB + u0 * 16;
    const char* gB = (const char*)g_Wq + (size_t)(bn + r) * ROWB + u0 * 16;
    uint32_t sAaddr[4], sBaddr[4];
#pragma unroll
    for (int j = 0; j < 4; j++) {
        const uint32_t p = (uint32_t)((u0 + j) ^ (r & 7)) * 16;
        sAaddr[j] = sbase + (uint32_t)r * 128 + p;
        sBaddr[j] = sAaddr[j] + A_BYTES;
    }

    // ---- warp tiling: 2 (M) x 4 (N); warp tile 64x32 ----
    const int warp_m = (wid & 1) << 6;
    const int warp_n = (wid >> 1) << 5;
    const int lr = lane & 7;
    const int aRow = warp_m + ((lane >> 3) & 1) * 8 + lr;
    const int aHi  = lane >> 4;
    const int aX   = aRow & 7;
    const uint32_t aBase = (uint32_t)aRow * 128;
    const int bRow = warp_n + (lane >> 4) * 8 + lr;
    const int bHi  = (lane >> 3) & 1;
    const int bX   = bRow & 7;
    const uint32_t bBase = (uint32_t)A_BYTES + (uint32_t)bRow * 128;

    float acc[4][4][4];
#pragma unroll
    for (int i = 0; i < 4; i++)
#pragma unroll
        for (int j = 0; j < 4; j++)
#pragma unroll
            for (int q = 0; q < 4; q++) acc[i][j][q] = 0.0f;

    auto issue_load = [&](int c, uint32_t so) {
        const size_t go = (size_t)c * BKB;
#pragma unroll
        for (int j = 0; j < 4; j++) CPA16(sAaddr[j] + so, gA + go + j * 16);
#pragma unroll
        for (int j = 0; j < 4; j++) CPA16(sBaddr[j] + so, gB + go + j * 16);
    };

    issue_load(0, 0 * STAGE_BYTES); CP_COMMIT();
    issue_load(1, 1 * STAGE_BYTES); CP_COMMIT();
    issue_load(2, 2 * STAGE_BYTES); CP_COMMIT();

    int stage = 0, nstage = 3;
    for (int c = 0; c < NCHUNK; c++) {
        CP_WAIT(2);
        __syncthreads();
        if (c + 3 < NCHUNK) issue_load(c + 3, (uint32_t)nstage * STAGE_BYTES);
        CP_COMMIT();

        const uint32_t st = sbase + (uint32_t)stage * STAGE_BYTES;
        // 4 k-steps of 32B (= 16 bf16) each
#pragma unroll
        for (int s = 0; s < 4; s++) {
            uint32_t a[4][4], b[4][2];
            const uint32_t ua = (uint32_t)((((s << 1) + aHi) ^ aX) * 16);
#pragma unroll
            for (int mt = 0; mt < 4; mt++) {
                const uint32_t ad = st + aBase + (uint32_t)mt * 2048 + ua;
                LDSM4(a[mt][0], a[mt][1], a[mt][2], a[mt][3], ad);
            }
            const uint32_t ub = (uint32_t)((((s << 1) + bHi) ^ bX) * 16);
#pragma unroll
            for (int ng = 0; ng < 2; ng++) {
                const uint32_t bd = st + bBase + (uint32_t)ng * 2048 + ub;
                LDSM4(b[2 * ng][0], b[2 * ng][1], b[2 * ng + 1][0], b[2 * ng + 1][1], bd);
            }
#pragma unroll
            for (int mt = 0; mt < 4; mt++)
#pragma unroll
                for (int nt = 0; nt < 4; nt++)
                    HMMA(acc[mt][nt], a[mt], b[nt]);
        }

        if (++stage == STAGES) stage = 0;
        if (++nstage == STAGES) nstage = 0;
    }

    // ---- epilogue: y = acc * (sa*sw) + bias ----
#pragma unroll
    for (int mt = 0; mt < 4; mt++) {
        const int r0 = bm + warp_m + mt * 16 + (lane >> 2);
        const float sa0 = g_sa[r0];
        const float sa1 = g_sa[r0 + 8];
        float* o0 = out + (size_t)r0 * NDIM + bn;
        float* o1 = o0 + (size_t)8 * NDIM;
#pragma unroll
        for (int nt = 0; nt < 4; nt++) {
            const int ncol = warp_n + nt * 8 + ((lane & 3) << 1);
            const int n = bn + ncol;
            const float sw0 = g_sw[n], sw1 = g_sw[n + 1];
            const float b0 = __ldg(bias + n), b1 = __ldg(bias + n + 1);
            const float* cc = acc[mt][nt];
            float2 y0, y1;
            y0.x = cc[0] * (sa0 * sw0) + b0;
            y0.y = cc[1] * (sa0 * sw1) + b1;
            y1.x = cc[2] * (sa1 * sw0) + b0;
            y1.y = cc[3] * (sa1 * sw1) + b1;
            *reinterpret_cast<float2*>(o0 + ncol) = y0;
            *reinterpret_cast<float2*>(o1 + ncol) = y1;
        }
    }
}

// ---------------- host launch ----------------
extern "C" void kernel_launch(void* const* d_in, const int* in_sizes, int n_in,
                              void* d_out, int out_size) {
    (void)in_sizes; (void)n_in; (void)out_size;
    const float* x    = (const float*)d_in[0];
    const float* w    = (const float*)d_in[1];
    const float* bias = (const float*)d_in[2];
    float* out = (float*)d_out;

    quant_x_kernel<<<MDIM, 256>>>(x);
    quant_w_kernel<<<NDIM, 256>>>(w);

    static int smem_set = 0;
    if (!smem_set) {
        cudaFuncSetAttribute(gemm_kernel, cudaFuncAttributeMaxDynamicSharedMemorySize,
                             GEMM_SMEM);
        smem_set = 1;
    }
    gemm_kernel<<<dim3(NDIM / BN, MDIM / BM), 256, GEMM_SMEM>>>(bias, out);
}

// round 5
// speedup vs baseline: 2.5184x; 1.4113x over previous
#include <cuda_runtime.h>
#include <cuda_bf16.h>
#include <cstdint>
#include <cstddef>

static constexpr int MDIM = 8192;   // 4*2048 tokens
static constexpr int KDIM = 4096;
static constexpr int NDIM = 4096;

// ---------------- scratch (alloc-free: __device__ globals) ----------------
__device__ __align__(1024) __nv_bfloat16 g_Aq[(size_t)MDIM * KDIM]; // Xq - zp (exact ints)
__device__ __align__(1024) __nv_bfloat16 g_Wq[(size_t)NDIM * KDIM]; // Wq (exact ints)
__device__ float g_sa[MDIM];   // activation scale per token
__device__ float g_sw[NDIM];   // weight scale per row

// ---------------- PTX helpers ----------------
__device__ __forceinline__ uint32_t smem_u32(const void* p) {
    uint32_t a;
    asm("{ .reg .u64 t; cvta.to.shared.u64 t, %1; cvt.u32.u64 %0, t; }" : "=r"(a) : "l"(p));
    return a;
}
#define CPA16(s, g) asm volatile("cp.async.cg.shared.global [%0], [%1], 16;" :: "r"(s), "l"(g))
#define CP_COMMIT()  asm volatile("cp.async.commit_group;" ::: "memory")
#define CP_WAIT(n)   asm volatile("cp.async.wait_group %0;" :: "n"(n) : "memory")
#define LDSM4(r0, r1, r2, r3, addr) \
    asm volatile("ldmatrix.sync.aligned.m8n8.x4.shared.b16 {%0,%1,%2,%3}, [%4];" \
                 : "=r"(r0), "=r"(r1), "=r"(r2), "=r"(r3) : "r"(addr))
#define HMMA(c, a, b) \
    asm volatile("mma.sync.aligned.m16n8k16.row.col.f32.bf16.bf16.f32 " \
                 "{%0,%1,%2,%3}, {%4,%5,%6,%7}, {%8,%9}, {%0,%1,%2,%3};" \
                 : "+f"((c)[0]), "+f"((c)[1]), "+f"((c)[2]), "+f"((c)[3]) \
                 : "r"((a)[0]), "r"((a)[1]), "r"((a)[2]), "r"((a)[3]), \
                   "r"((b)[0]), "r"((b)[1]))

// ---------------- quantization kernels (proven correct) ----------------
__global__ void __launch_bounds__(256) quant_x_kernel(const float* __restrict__ x) {
    const int m = blockIdx.x;
    const int t = threadIdx.x;
    const float4* row = reinterpret_cast<const float4*>(x + (size_t)m * KDIM);
    float4 v[4];
    float mn = 3.4e38f, mx = -3.4e38f;
#pragma unroll
    for (int i = 0; i < 4; i++) {
        v[i] = row[t * 4 + i];
        mn = fminf(mn, fminf(fminf(v[i].x, v[i].y), fminf(v[i].z, v[i].w)));
        mx = fmaxf(mx, fmaxf(fmaxf(v[i].x, v[i].y), fmaxf(v[i].z, v[i].w)));
    }
#pragma unroll
    for (int o = 16; o > 0; o >>= 1) {
        mn = fminf(mn, __shfl_xor_sync(0xffffffffu, mn, o));
        mx = fmaxf(mx, __shfl_xor_sync(0xffffffffu, mx, o));
    }
    __shared__ float smn[8], smx[8];
    if ((t & 31) == 0) { smn[t >> 5] = mn; smx[t >> 5] = mx; }
    __syncthreads();
    mn = smn[0]; mx = smx[0];
#pragma unroll
    for (int i = 1; i < 8; i++) { mn = fminf(mn, smn[i]); mx = fmaxf(mx, smx[i]); }

    const float rng = mx - mn;
    const float s = (rng > 0.0f) ? __fdiv_rn(rng, 255.0f) : 1.0f;
    const float zp = rintf(__fdiv_rn(-mn, s));

    __nv_bfloat16* o = g_Aq + (size_t)m * KDIM + t * 16;
#pragma unroll
    for (int i = 0; i < 4; i++) {
        float q0 = fminf(fmaxf(rintf(__fdiv_rn(v[i].x, s)) + zp, 0.0f), 255.0f) - zp;
        float q1 = fminf(fmaxf(rintf(__fdiv_rn(v[i].y, s)) + zp, 0.0f), 255.0f) - zp;
        float q2 = fminf(fmaxf(rintf(__fdiv_rn(v[i].z, s)) + zp, 0.0f), 255.0f) - zp;
        float q3 = fminf(fmaxf(rintf(__fdiv_rn(v[i].w, s)) + zp, 0.0f), 255.0f) - zp;
        __nv_bfloat162 p0 = __halves2bfloat162(__float2bfloat16_rn(q0), __float2bfloat16_rn(q1));
        __nv_bfloat162 p1 = __halves2bfloat162(__float2bfloat16_rn(q2), __float2bfloat16_rn(q3));
        *reinterpret_cast<__nv_bfloat162*>(o + i * 4)     = p0;
        *reinterpret_cast<__nv_bfloat162*>(o + i * 4 + 2) = p1;
    }
    if (t == 0) g_sa[m] = s;
}

__global__ void __launch_bounds__(256) quant_w_kernel(const float* __restrict__ w) {
    const int n = blockIdx.x;
    const int t = threadIdx.x;
    const float4* row = reinterpret_cast<const float4*>(w + (size_t)n * KDIM);
    float4 v[4];
    float amax = 0.0f;
#pragma unroll
    for (int i = 0; i < 4; i++) {
        v[i] = row[t * 4 + i];
        amax = fmaxf(amax, fmaxf(fmaxf(fabsf(v[i].x), fabsf(v[i].y)),
                                 fmaxf(fabsf(v[i].z), fabsf(v[i].w))));
    }
#pragma unroll
    for (int o = 16; o > 0; o >>= 1)
        amax = fmaxf(amax, __shfl_xor_sync(0xffffffffu, amax, o));
    __shared__ float sm[8];
    if ((t & 31) == 0) sm[t >> 5] = amax;
    __syncthreads();
    amax = sm[0];
#pragma unroll
    for (int i = 1; i < 8; i++) amax = fmaxf(amax, sm[i]);

    const float s = (amax > 0.0f) ? __fdiv_rn(amax, 127.0f) : 1.0f;

    __nv_bfloat16* o = g_Wq + (size_t)n * KDIM + t * 16;
#pragma unroll
    for (int i = 0; i < 4; i++) {
        float q0 = fminf(fmaxf(rintf(__fdiv_rn(v[i].x, s)), -127.0f), 127.0f);
        float q1 = fminf(fmaxf(rintf(__fdiv_rn(v[i].y, s)), -127.0f), 127.0f);
        float q2 = fminf(fmaxf(rintf(__fdiv_rn(v[i].z, s)), -127.0f), 127.0f);
        float q3 = fminf(fmaxf(rintf(__fdiv_rn(v[i].w, s)), -127.0f), 127.0f);
        __nv_bfloat162 p0 = __halves2bfloat162(__float2bfloat16_rn(q0), __float2bfloat16_rn(q1));
        __nv_bfloat162 p1 = __halves2bfloat162(__float2bfloat16_rn(q2), __float2bfloat16_rn(q3));
        *reinterpret_cast<__nv_bfloat162*>(o + i * 4)     = p0;
        *reinterpret_cast<__nv_bfloat162*>(o + i * 4 + 2) = p1;
    }
    if (t == 0) g_sw[n] = s;
}

// ---------------- GEMM: bf16 HMMA, 128x128x64(elts), 512 thr, 16 warps ----------------
static constexpr int BM = 128, BN = 128;
static constexpr int BKB = 128;                            // K bytes per chunk (64 bf16)
static constexpr int STAGES = 4;
static constexpr int NCHUNK = (KDIM * 2) / BKB;            // 64
static constexpr int A_BYTES = BM * BKB;                   // 16384
static constexpr int STAGE_BYTES = (BM + BN) * BKB;        // 32768
static constexpr uint32_t GEMM_SMEM = STAGES * STAGE_BYTES;  // 131072
static constexpr size_t ROWB = (size_t)KDIM * 2;           // bytes per logical row

__global__ void __launch_bounds__(512)
gemm_kernel(const float* __restrict__ bias, float* __restrict__ out) {
    extern __shared__ int8_t smem[];
    const uint32_t sbase = smem_u32(smem);
    const int tid = threadIdx.x;
    const int wid = tid >> 5;
    const int lane = tid & 31;
    const int bm = blockIdx.y * BM;
    const int bn = blockIdx.x * BN;

    // ---- cp.async: rows of 128B = 8 x 16B units, phys_unit = u ^ (row&7) ----
    const int r  = tid >> 2;            // 0..127
    const int u0 = (tid & 3) * 2;       // first of 2 units
    const char* gA = (const char*)g_Aq + (size_t)(bm + r) * ROWB + u0 * 16;
    const char* gB = (const char*)g_Wq + (size_t)(bn + r) * ROWB + u0 * 16;
    uint32_t sAaddr[2], sBaddr[2];
#pragma unroll
    for (int j = 0; j < 2; j++) {
        const uint32_t p = (uint32_t)((u0 + j) ^ (r & 7)) * 16;
        sAaddr[j] = sbase + (uint32_t)r * 128 + p;
        sBaddr[j] = sAaddr[j] + A_BYTES;
    }

    // ---- warp tiling: 4 (M) x 4 (N); warp tile 32x32 ----
    const int warp_m = (wid & 3) << 5;    // 0/32/64/96
    const int warp_n = (wid >> 2) << 5;   // 0/32/64/96
    const int lr = lane & 7;
    const int aRow = warp_m + ((lane >> 3) & 1) * 8 + lr;
    const int aHi  = lane >> 4;
    const int aX   = aRow & 7;
    const uint32_t aBase = (uint32_t)aRow * 128;
    const int bRow = warp_n + (lane >> 4) * 8 + lr;
    const int bHi  = (lane >> 3) & 1;
    const int bX   = bRow & 7;
    const uint32_t bBase = (uint32_t)A_BYTES + (uint32_t)bRow * 128;

    float acc[2][4][4];
#pragma unroll
    for (int i = 0; i < 2; i++)
#pragma unroll
        for (int j = 0; j < 4; j++)
#pragma unroll
            for (int q = 0; q < 4; q++) acc[i][j][q] = 0.0f;

    auto issue_load = [&](int c, uint32_t so) {
        const size_t go = (size_t)c * BKB;
#pragma unroll
        for (int j = 0; j < 2; j++) CPA16(sAaddr[j] + so, gA + go + j * 16);
#pragma unroll
        for (int j = 0; j < 2; j++) CPA16(sBaddr[j] + so, gB + go + j * 16);
    };

    issue_load(0, 0 * STAGE_BYTES); CP_COMMIT();
    issue_load(1, 1 * STAGE_BYTES); CP_COMMIT();
    issue_load(2, 2 * STAGE_BYTES); CP_COMMIT();

    int stage = 0, nstage = 3;
    for (int c = 0; c < NCHUNK; c++) {
        CP_WAIT(2);
        __syncthreads();
        if (c + 3 < NCHUNK) issue_load(c + 3, (uint32_t)nstage * STAGE_BYTES);
        CP_COMMIT();

        const uint32_t st = sbase + (uint32_t)stage * STAGE_BYTES;
        // 4 k-steps of 32B (= 16 bf16) each
#pragma unroll
        for (int s = 0; s < 4; s++) {
            uint32_t a[2][4], b[4][2];
            const uint32_t ua = (uint32_t)((((s << 1) + aHi) ^ aX) * 16);
#pragma unroll
            for (int mt = 0; mt < 2; mt++) {
                const uint32_t ad = st + aBase + (uint32_t)mt * 2048 + ua;
                LDSM4(a[mt][0], a[mt][1], a[mt][2], a[mt][3], ad);
            }
            const uint32_t ub = (uint32_t)((((s << 1) + bHi) ^ bX) * 16);
#pragma unroll
            for (int ng = 0; ng < 2; ng++) {
                const uint32_t bd = st + bBase + (uint32_t)ng * 2048 + ub;
                LDSM4(b[2 * ng][0], b[2 * ng][1], b[2 * ng + 1][0], b[2 * ng + 1][1], bd);
            }
#pragma unroll
            for (int mt = 0; mt < 2; mt++)
#pragma unroll
                for (int nt = 0; nt < 4; nt++)
                    HMMA(acc[mt][nt], a[mt], b[nt]);
        }

        if (++stage == STAGES) stage = 0;
        if (++nstage == STAGES) nstage = 0;
    }

    // ---- epilogue: y = acc * (sa*sw) + bias ----
#pragma unroll
    for (int mt = 0; mt < 2; mt++) {
        const int r0 = bm + warp_m + mt * 16 + (lane >> 2);
        const float sa0 = g_sa[r0];
        const float sa1 = g_sa[r0 + 8];
        float* o0 = out + (size_t)r0 * NDIM + bn;
        float* o1 = o0 + (size_t)8 * NDIM;
#pragma unroll
        for (int nt = 0; nt < 4; nt++) {
            const int ncol = warp_n + nt * 8 + ((lane & 3) << 1);
            const int n = bn + ncol;
            const float sw0 = g_sw[n], sw1 = g_sw[n + 1];
            const float b0 = __ldg(bias + n), b1 = __ldg(bias + n + 1);
            const float* cc = acc[mt][nt];
            float2 y0, y1;
            y0.x = cc[0] * (sa0 * sw0) + b0;
            y0.y = cc[1] * (sa0 * sw1) + b1;
            y1.x = cc[2] * (sa1 * sw0) + b0;
            y1.y = cc[3] * (sa1 * sw1) + b1;
            *reinterpret_cast<float2*>(o0 + ncol) = y0;
            *reinterpret_cast<float2*>(o1 + ncol) = y1;
        }
    }
}

// ---------------- host launch ----------------
extern "C" void kernel_launch(void* const* d_in, const int* in_sizes, int n_in,
                              void* d_out, int out_size) {
    (void)in_sizes; (void)n_in; (void)out_size;
    const float* x    = (const float*)d_in[0];
    const float* w    = (const float*)d_in[1];
    const float* bias = (const float*)d_in[2];
    float* out = (float*)d_out;

    quant_x_kernel<<<MDIM, 256>>>(x);
    quant_w_kernel<<<NDIM, 256>>>(w);

    static int smem_set = 0;
    if (!smem_set) {
        cudaFuncSetAttribute(gemm_kernel, cudaFuncAttributeMaxDynamicSharedMemorySize,
                             GEMM_SMEM);
        smem_set = 1;
    }
    gemm_kernel<<<dim3(NDIM / BN, MDIM / BM), 512, GEMM_SMEM>>>(bias, out);
}